// round 4
// baseline (speedup 1.0000x reference)
#include <cuda_runtime.h>
#include <float.h>
#include <math.h>

#define NB 16
#define NP 1024
#define NC 91
#define MAX_DET 100
#define SCORE_THRESH 0.05f
#define NMS_THRESH 0.5f
#define BBOX_CLIP 4.135166556742356f  /* log(1000/16) */

// ---------------- scratch (no allocations allowed) ----------------
__device__ float  g_scores[NB * NP];
__device__ int    g_labels[NB * NP];   // 0 if invalid, else class id 1..90
__device__ float4 g_boxes[NB * NP];

// ---------------- Kernel A: softmax-max/argmax + decode + clip ----------------
// One warp per proposal. Lanes cover classes {lane, lane+32, lane+64}.
__global__ void score_decode_kernel(const float* __restrict__ logits,
                                    const float* __restrict__ deltas,
                                    const float* __restrict__ props,
                                    const int*   __restrict__ imsz) {
    int gw   = (blockIdx.x * blockDim.x + threadIdx.x) >> 5;
    int lane = threadIdx.x & 31;
    if (gw >= NB * NP) return;

    const float* row = logits + (size_t)gw * NC;
    float l0 = row[lane];
    float l1 = row[lane + 32];
    bool  has2 = (lane < NC - 64);           // lane < 27
    float l2 = has2 ? row[lane + 64] : -FLT_MAX;

    // local argmax with first-index tie break
    float bv = l0; int bi = lane;
    if (l1 > bv) { bv = l1; bi = lane + 32; }
    if (l2 > bv) { bv = l2; bi = lane + 64; }
    #pragma unroll
    for (int o = 16; o; o >>= 1) {
        float ov = __shfl_down_sync(0xffffffffu, bv, o);
        int   oi = __shfl_down_sync(0xffffffffu, bi, o);
        if (ov > bv || (ov == bv && oi < bi)) { bv = ov; bi = oi; }
    }
    bv = __shfl_sync(0xffffffffu, bv, 0);
    bi = __shfl_sync(0xffffffffu, bi, 0);

    float s = expf(l0 - bv) + expf(l1 - bv) + (has2 ? expf(l2 - bv) : 0.0f);
    #pragma unroll
    for (int o = 16; o; o >>= 1) s += __shfl_down_sync(0xffffffffu, s, o);

    if (lane == 0) {
        float score = 1.0f / s;
        int label = bi;
        int b = gw / NP;
        int valid = (label > 0) && (score > SCORE_THRESH);

        const float* p = props + (size_t)gw * 4;
        float x1 = p[0], y1 = p[1], x2 = p[2], y2 = p[3];
        float w = x2 - x1, h = y2 - y1;
        float cx = x1 + 0.5f * w, cy = y1 + 0.5f * h;

        const float* dd = deltas + (size_t)gw * (NC * 4) + 4 * label;
        float dx = dd[0], dy = dd[1];
        float dw = fminf(dd[2], BBOX_CLIP), dh = fminf(dd[3], BBOX_CLIP);
        float pcx = dx * w + cx, pcy = dy * h + cy;
        float pw = expf(dw) * w, ph = expf(dh) * h;
        float bx1 = pcx - 0.5f * pw, by1 = pcy - 0.5f * ph;
        float bx2 = pcx + 0.5f * pw, by2 = pcy + 0.5f * ph;

        float hb = (float)imsz[b * 2 + 0];
        float wb = (float)imsz[b * 2 + 1];
        bx1 = fminf(fmaxf(bx1, 0.0f), wb);
        by1 = fminf(fmaxf(by1, 0.0f), hb);
        bx2 = fminf(fmaxf(bx2, 0.0f), wb);
        by2 = fminf(fmaxf(by2, 0.0f), hb);

        g_boxes[gw]  = make_float4(bx1, by1, bx2, by2);
        g_scores[gw] = score;
        g_labels[gw] = valid ? label : 0;
    }
}

// ---------------- Fused Kernel B: per-image NMS + top-100 (no sorts) -----------
// One CTA of 1024 threads per image. Warp w handles classes {w+1, w+33, w+65}.
__global__ __launch_bounds__(1024) void nms_topk_kernel(float* __restrict__ out) {
    const int b    = blockIdx.x;
    const int t    = threadIdx.x;
    const int warp = t >> 5;
    const int lane = t & 31;

    __shared__ float4            s_box[NP];     // 16 KB (raw clipped boxes)
    __shared__ float             s_score[NP];   //  4 KB
    __shared__ unsigned char     s_label[NP];   //  1 KB (0 = invalid)
    __shared__ unsigned char     s_kept[NP];    //  1 KB
    __shared__ unsigned long long s_list[NP];   //  8 KB (compacted kept keys)
    __shared__ float s_red[32];
    __shared__ float s_K;
    __shared__ int   s_cnt;

    // ---- stage image data into smem (coalesced) ----
    const int g = b * NP + t;
    float4 bx    = g_boxes[g];
    float  sc    = g_scores[g];
    int    lab   = g_labels[g];
    s_box[t]   = bx;
    s_score[t] = sc;
    s_label[t] = (unsigned char)lab;
    s_kept[t]  = 0;
    if (t == 0) s_cnt = 0;

    // ---- max_coord over valid boxes (invalid contribute 0) ----
    float mc = (lab != 0) ? fmaxf(fmaxf(bx.x, bx.y), fmaxf(bx.z, bx.w)) : 0.0f;
    #pragma unroll
    for (int o = 16; o; o >>= 1)
        mc = fmaxf(mc, __shfl_xor_sync(0xffffffffu, mc, o));
    if (lane == 0) s_red[warp] = mc;
    __syncthreads();                                   // barrier 1
    if (t < 32) {
        float v = s_red[t];
        #pragma unroll
        for (int o = 16; o; o >>= 1)
            v = fmaxf(v, __shfl_xor_sync(0xffffffffu, v, o));
        if (t == 0) s_K = v + 1.0f;
    }
    __syncthreads();                                   // barrier 2
    const float K = s_K;

    // ---- per-class greedy NMS (iterative max selection == sorted greedy) ----
    for (int c = warp + 1; c <= 90; c += 32) {
        const float off = (float)c * K;   // label * (max_coord + 1), reference FP order

        // alive mask: bit j <-> entry e = j*32+lane of class c
        unsigned alive = 0;
        #pragma unroll
        for (int j = 0; j < 32; ++j)
            if (s_label[j * 32 + lane] == (unsigned char)c) alive |= (1u << j);

        while (true) {
            // per-lane min key (ds asc = score desc; tie -> smaller j = smaller idx)
            unsigned best_ds = 0xffffffffu; int best_j = -1;
            unsigned am = alive;
            while (am) {
                int j = __ffs(am) - 1; am &= am - 1;
                unsigned ds = ~__float_as_uint(s_score[j * 32 + lane]);
                if (ds < best_ds) { best_ds = ds; best_j = j; }
            }
            unsigned long long key = (best_j < 0) ? ~0ULL
                : (((unsigned long long)best_ds << 10) |
                   (unsigned long long)(unsigned)(best_j * 32 + lane));
            #pragma unroll
            for (int o = 16; o; o >>= 1) {
                unsigned long long ok = __shfl_xor_sync(0xffffffffu, key, o);
                if (ok < key) key = ok;
            }
            if (key == ~0ULL) break;

            int e = (int)(key & 1023ULL);
            if ((e & 31) == lane) {
                alive &= ~(1u << (e >> 5));
                s_kept[e] = 1;
            }
            float4 A = s_box[e];                       // broadcast read
            A.x += off; A.y += off; A.z += off; A.w += off;
            float areaA = (A.z - A.x) * (A.w - A.y);

            am = alive;
            while (am) {
                int j = __ffs(am) - 1; am &= am - 1;
                int e2 = j * 32 + lane;
                float4 Bx = s_box[e2];
                Bx.x += off; Bx.y += off; Bx.z += off; Bx.w += off;
                float areaB = (Bx.z - Bx.x) * (Bx.w - Bx.y);
                float ltx = fmaxf(A.x, Bx.x), lty = fmaxf(A.y, Bx.y);
                float rbx = fminf(A.z, Bx.z), rby = fminf(A.w, Bx.w);
                float wx = fmaxf(rbx - ltx, 0.0f), wy = fmaxf(rby - lty, 0.0f);
                float inter = wx * wy;
                float uni = areaA + areaB - inter;
                float iou = inter / (uni + 1e-9f);
                if (iou > NMS_THRESH) alive &= ~(1u << j);
            }
        }
    }
    __syncthreads();                                   // barrier 3

    // ---- compact kept keys ----
    unsigned long long mykey = ~0ULL;
    if (s_kept[t]) {
        mykey = (((unsigned long long)(~__float_as_uint(sc))) << 10) |
                (unsigned long long)(unsigned)t;
        int p = atomicAdd(&s_cnt, 1);
        s_list[p] = mykey;
    }
    __syncthreads();                                   // barrier 4
    const int M = s_cnt;
    const int filled = M < MAX_DET ? M : MAX_DET;

    float* boxes_out  = out;
    float* scores_out = out + NB * MAX_DET * 4;
    float* labels_out = out + NB * MAX_DET * 5;

    // default-fill the empty slots (disjoint from real writes -> race-free)
    if (t >= filled && t < MAX_DET) {
        int base = b * MAX_DET + t;
        boxes_out[base * 4 + 0] = 0.0f;
        boxes_out[base * 4 + 1] = 0.0f;
        boxes_out[base * 4 + 2] = 0.0f;
        boxes_out[base * 4 + 3] = 0.0f;
        scores_out[base] = 0.0f;
        labels_out[base] = -1.0f;
    }

    // rank selection: rank = #{ keys strictly smaller }, unique keys -> unique ranks
    if (mykey != ~0ULL) {
        int rank = 0;
        for (int j = 0; j < M; ++j)
            rank += (s_list[j] < mykey);
        if (rank < MAX_DET) {
            int base = b * MAX_DET + rank;
            boxes_out[base * 4 + 0] = bx.x;
            boxes_out[base * 4 + 1] = bx.y;
            boxes_out[base * 4 + 2] = bx.z;
            boxes_out[base * 4 + 3] = bx.w;
            scores_out[base] = sc;
            labels_out[base] = (float)lab;
        }
    }
}

// ---------------- launch ----------------
extern "C" void kernel_launch(void* const* d_in, const int* in_sizes, int n_in,
                              void* d_out, int out_size) {
    const float* class_logits  = (const float*)d_in[0];
    const float* bbox_deltas   = (const float*)d_in[1];
    const float* roi_proposals = (const float*)d_in[2];
    const int*   image_sizes   = (const int*)d_in[3];
    float* out = (float*)d_out;

    int total_warps = NB * NP;
    int threads = 256;
    int blocks = (total_warps * 32 + threads - 1) / threads;
    score_decode_kernel<<<blocks, threads>>>(class_logits, bbox_deltas,
                                             roi_proposals, image_sizes);

    nms_topk_kernel<<<NB, 1024>>>(out);
}

// round 5
// speedup vs baseline: 1.7940x; 1.7940x over previous
#include <cuda_runtime.h>
#include <float.h>
#include <math.h>

#define NB 16
#define NP 1024
#define NC 91
#define MAX_DET 100
#define SCORE_THRESH 0.05f
#define NMS_THRESH 0.5f
#define BBOX_CLIP 4.135166556742356f  /* log(1000/16) */
#define BK 128                        /* bucket capacity per (image,class) */

// ---------------- scratch (no allocations allowed) ----------------
__device__ float  g_scores[NB * NP];
__device__ int    g_labels[NB * NP];           // 0 if invalid, else 1..90
__device__ float4 g_boxes[NB * NP];

__device__ int    g_bcnt[NB * 91];             // bucket counts
__device__ float4 g_bbox[NB * 91 * BK];        // bucket boxes (raw clipped)
__device__ float  g_bsc [NB * 91 * BK];        // bucket scores
__device__ int    g_bidx[NB * 91 * BK];        // bucket original idx (0..1023)
__device__ int    g_maxc[NB];                  // per-image max coord (float bits)
__device__ int    g_kcnt[NB];                  // kept count per image
__device__ unsigned long long g_klist[NB * NP];// kept keys per image

// ---------------- Kernel Z: reset counters ----------------
__global__ void zero_kernel() {
    int t = blockIdx.x * blockDim.x + threadIdx.x;
    if (t < NB * 91) g_bcnt[t] = 0;
    if (t < NB) { g_kcnt[t] = 0; g_maxc[t] = 0; }
}

// ---------------- Kernel A: softmax-max/argmax + decode + clip + bucket ----------------
// One warp per proposal. Lanes cover classes {lane, lane+32, lane+64}.
__global__ void score_decode_kernel(const float* __restrict__ logits,
                                    const float* __restrict__ deltas,
                                    const float* __restrict__ props,
                                    const int*   __restrict__ imsz) {
    int gw   = (blockIdx.x * blockDim.x + threadIdx.x) >> 5;
    int lane = threadIdx.x & 31;
    if (gw >= NB * NP) return;

    const float* row = logits + (size_t)gw * NC;
    float l0 = row[lane];
    float l1 = row[lane + 32];
    bool  has2 = (lane < NC - 64);           // lane < 27
    float l2 = has2 ? row[lane + 64] : -FLT_MAX;

    // local argmax with first-index tie break
    float bv = l0; int bi = lane;
    if (l1 > bv) { bv = l1; bi = lane + 32; }
    if (l2 > bv) { bv = l2; bi = lane + 64; }
    #pragma unroll
    for (int o = 16; o; o >>= 1) {
        float ov = __shfl_down_sync(0xffffffffu, bv, o);
        int   oi = __shfl_down_sync(0xffffffffu, bi, o);
        if (ov > bv || (ov == bv && oi < bi)) { bv = ov; bi = oi; }
    }
    bv = __shfl_sync(0xffffffffu, bv, 0);
    bi = __shfl_sync(0xffffffffu, bi, 0);

    float s = expf(l0 - bv) + expf(l1 - bv) + (has2 ? expf(l2 - bv) : 0.0f);
    #pragma unroll
    for (int o = 16; o; o >>= 1) s += __shfl_down_sync(0xffffffffu, s, o);

    if (lane == 0) {
        float score = 1.0f / s;
        int label = bi;
        int b = gw / NP;
        int valid = (label > 0) && (score > SCORE_THRESH);

        const float* p = props + (size_t)gw * 4;
        float x1 = p[0], y1 = p[1], x2 = p[2], y2 = p[3];
        float w = x2 - x1, h = y2 - y1;
        float cx = x1 + 0.5f * w, cy = y1 + 0.5f * h;

        const float* dd = deltas + (size_t)gw * (NC * 4) + 4 * label;
        float dx = dd[0], dy = dd[1];
        float dw = fminf(dd[2], BBOX_CLIP), dh = fminf(dd[3], BBOX_CLIP);
        float pcx = dx * w + cx, pcy = dy * h + cy;
        float pw = expf(dw) * w, ph = expf(dh) * h;
        float bx1 = pcx - 0.5f * pw, by1 = pcy - 0.5f * ph;
        float bx2 = pcx + 0.5f * pw, by2 = pcy + 0.5f * ph;

        float hb = (float)imsz[b * 2 + 0];
        float wb = (float)imsz[b * 2 + 1];
        bx1 = fminf(fmaxf(bx1, 0.0f), wb);
        by1 = fminf(fmaxf(by1, 0.0f), hb);
        bx2 = fminf(fmaxf(bx2, 0.0f), wb);
        by2 = fminf(fmaxf(by2, 0.0f), hb);

        g_boxes[gw]  = make_float4(bx1, by1, bx2, by2);
        g_scores[gw] = score;
        g_labels[gw] = valid ? label : 0;

        if (valid) {
            // exact max over valid box coords (all >= 0, float bits monotone)
            float mc = fmaxf(fmaxf(bx1, by1), fmaxf(bx2, by2));
            atomicMax(&g_maxc[b], __float_as_int(mc));
            int bc = b * 91 + label;
            int p2 = atomicAdd(&g_bcnt[bc], 1);
            if (p2 < BK) {
                int slot = bc * BK + p2;
                g_bbox[slot] = make_float4(bx1, by1, bx2, by2);
                g_bsc[slot]  = score;
                g_bidx[slot] = gw - b * NP;
            }
        }
    }
}

// ---------------- Kernel B: NMS, one warp per (image, class), registers only ----------------
__global__ __launch_bounds__(256) void nms_class_kernel() {
    int gwarp = (blockIdx.x * blockDim.x + threadIdx.x) >> 5;
    int lane  = threadIdx.x & 31;
    if (gwarp >= NB * 90) return;
    int b = gwarp / 90;
    int c = 1 + gwarp % 90;
    int bc = b * 91 + c;

    int n = g_bcnt[bc];
    if (n > BK) n = BK;
    if (n == 0) return;

    float K   = __int_as_float(g_maxc[b]) + 1.0f;
    float off = (float)c * K;    // label * (max_coord + 1), reference FP order

    float4 bxs[4]; float scs[4]; int idxs[4];
    unsigned alive = 0;
    #pragma unroll
    for (int j = 0; j < 4; ++j) {
        int e = j * 32 + lane;
        if (e < n) {
            float4 v = g_bbox[bc * BK + e];
            bxs[j] = make_float4(v.x + off, v.y + off, v.z + off, v.w + off);
            scs[j] = g_bsc[bc * BK + e];
            idxs[j] = g_bidx[bc * BK + e];
            alive |= (1u << j);
        } else {
            bxs[j] = make_float4(0.f, 0.f, 0.f, 0.f);
            scs[j] = 0.f; idxs[j] = 0;
        }
    }

    unsigned keptm = 0;
    while (true) {
        // per-lane best alive key: (~score_bits, orig_idx, slot)
        unsigned long long best = ~0ULL;
        #pragma unroll
        for (int j = 0; j < 4; ++j) {
            if (alive & (1u << j)) {
                unsigned long long k =
                    ((unsigned long long)(~__float_as_uint(scs[j])) << 20) |
                    ((unsigned long long)(unsigned)idxs[j] << 10) |
                    (unsigned long long)(unsigned)(j * 32 + lane);
                if (k < best) best = k;
            }
        }
        #pragma unroll
        for (int o = 16; o; o >>= 1) {
            unsigned long long ob = __shfl_xor_sync(0xffffffffu, best, o);
            if (ob < best) best = ob;
        }
        if (best == ~0ULL) break;

        int e   = (int)(best & 1023ULL);
        int js  = e >> 5;
        int src = e & 31;
        float4 own = (js == 0) ? bxs[0] : (js == 1) ? bxs[1] : (js == 2) ? bxs[2] : bxs[3];
        float4 A;
        A.x = __shfl_sync(0xffffffffu, own.x, src);
        A.y = __shfl_sync(0xffffffffu, own.y, src);
        A.z = __shfl_sync(0xffffffffu, own.z, src);
        A.w = __shfl_sync(0xffffffffu, own.w, src);
        if (lane == src) {
            alive &= ~(1u << js);
            keptm |= (1u << js);
        }
        float areaA = (A.z - A.x) * (A.w - A.y);

        #pragma unroll
        for (int j = 0; j < 4; ++j) {
            if (alive & (1u << j)) {
                float4 Bx = bxs[j];
                float areaB = (Bx.z - Bx.x) * (Bx.w - Bx.y);
                float ltx = fmaxf(A.x, Bx.x), lty = fmaxf(A.y, Bx.y);
                float rbx = fminf(A.z, Bx.z), rby = fminf(A.w, Bx.w);
                float wx = fmaxf(rbx - ltx, 0.0f), wy = fmaxf(rby - lty, 0.0f);
                float inter = wx * wy;
                float iou = inter / (areaA + areaB - inter + 1e-9f);
                if (iou > NMS_THRESH) alive &= ~(1u << j);
            }
        }
    }

    // append kept keys to the image's list
    #pragma unroll
    for (int j = 0; j < 4; ++j) {
        unsigned bal = __ballot_sync(0xffffffffu, (keptm >> j) & 1u);
        if (bal) {
            int leader = __ffs(bal) - 1;
            int basep = 0;
            if (lane == leader) basep = atomicAdd(&g_kcnt[b], __popc(bal));
            basep = __shfl_sync(0xffffffffu, basep, leader);
            if ((keptm >> j) & 1u) {
                int p = basep + __popc(bal & ((1u << lane) - 1u));
                g_klist[b * NP + p] =
                    ((unsigned long long)(~__float_as_uint(scs[j])) << 10) |
                    (unsigned long long)(unsigned)idxs[j];
            }
        }
    }
}

// ---------------- Kernel C: per-image top-100 by rank counting ----------------
// 8 CTAs per image, 128 threads each; CTA handles 128 kept entries.
__global__ __launch_bounds__(128) void topk_rank_kernel(float* __restrict__ out) {
    const int img  = blockIdx.x >> 3;
    const int part = blockIdx.x & 7;
    const int t    = threadIdx.x;

    __shared__ unsigned long long s_keys[NP];

    int M = g_kcnt[img];
    if (M > NP) M = NP;
    for (int i = t; i < M; i += 128) s_keys[i] = g_klist[img * NP + i];
    __syncthreads();

    float* boxes_out  = out;
    float* scores_out = out + NB * MAX_DET * 4;
    float* labels_out = out + NB * MAX_DET * 5;

    int filled = M < MAX_DET ? M : MAX_DET;
    if (part == 0 && t >= filled && t < MAX_DET) {
        int base = img * MAX_DET + t;
        boxes_out[base * 4 + 0] = 0.0f;
        boxes_out[base * 4 + 1] = 0.0f;
        boxes_out[base * 4 + 2] = 0.0f;
        boxes_out[base * 4 + 3] = 0.0f;
        scores_out[base] = 0.0f;
        labels_out[base] = -1.0f;
    }

    int ei = part * 128 + t;
    if (ei < M) {
        unsigned long long mykey = s_keys[ei];
        int rank = 0;
        #pragma unroll 4
        for (int j = 0; j < M; ++j) rank += (s_keys[j] < mykey);
        if (rank < MAX_DET) {
            int idx = (int)(mykey & 1023ULL);
            int g = img * NP + idx;
            float4 v = g_boxes[g];
            int base = img * MAX_DET + rank;
            boxes_out[base * 4 + 0] = v.x;
            boxes_out[base * 4 + 1] = v.y;
            boxes_out[base * 4 + 2] = v.z;
            boxes_out[base * 4 + 3] = v.w;
            scores_out[base] = g_scores[g];
            labels_out[base] = (float)g_labels[g];
        }
    }
}

// ---------------- launch ----------------
extern "C" void kernel_launch(void* const* d_in, const int* in_sizes, int n_in,
                              void* d_out, int out_size) {
    const float* class_logits  = (const float*)d_in[0];
    const float* bbox_deltas   = (const float*)d_in[1];
    const float* roi_proposals = (const float*)d_in[2];
    const int*   image_sizes   = (const int*)d_in[3];
    float* out = (float*)d_out;

    zero_kernel<<<3, 512>>>();

    int total_warps = NB * NP;
    int threads = 256;
    int blocks = (total_warps * 32 + threads - 1) / threads;
    score_decode_kernel<<<blocks, threads>>>(class_logits, bbox_deltas,
                                             roi_proposals, image_sizes);

    int nmsWarps = NB * 90;
    int nmsBlocks = (nmsWarps * 32 + 255) / 256;
    nms_class_kernel<<<nmsBlocks, 256>>>();

    topk_rank_kernel<<<NB * 8, 128>>>(out);
}

// round 6
// speedup vs baseline: 1.9789x; 1.1031x over previous
#include <cuda_runtime.h>
#include <float.h>
#include <math.h>

#define NB 16
#define NP 1024
#define NC 91
#define MAX_DET 100
#define SCORE_THRESH 0.05f
#define NMS_THRESH 0.5f
#define BBOX_CLIP 4.135166556742356f  /* log(1000/16) */
#define BK 128                        /* bucket capacity per (image,class) */

// ---------------- scratch (no allocations allowed) ----------------
__device__ float  g_scores[NB * NP];
__device__ int    g_labels[NB * NP];           // 0 if invalid, else 1..90
__device__ float4 g_boxes[NB * NP];

__device__ int    g_bcnt[NB * 91];             // bucket counts
__device__ float4 g_bbox[NB * 91 * BK];        // bucket boxes (raw clipped)
__device__ float  g_bsc [NB * 91 * BK];        // bucket scores
__device__ int    g_bidx[NB * 91 * BK];        // bucket original idx (0..1023)
__device__ int    g_maxc[NB];                  // per-image max coord (float bits)
__device__ int    g_kkc[NB * 91];              // kept count per (image,class)
__device__ unsigned long long g_kseg[NB * 91 * BK]; // kept keys per (image,class)

// ---------------- Kernel Z: reset counters ----------------
__global__ void zero_kernel() {
    int t = blockIdx.x * blockDim.x + threadIdx.x;
    if (t < NB * 91) g_bcnt[t] = 0;
    if (t < NB) g_maxc[t] = 0;
}

// ---------------- Kernel A: softmax-max/argmax + decode + clip + bucket ----------------
// One warp per proposal. Lanes cover classes {lane, lane+32, lane+64}.
__global__ void score_decode_kernel(const float* __restrict__ logits,
                                    const float* __restrict__ deltas,
                                    const float* __restrict__ props,
                                    const int*   __restrict__ imsz) {
    int gw   = (blockIdx.x * blockDim.x + threadIdx.x) >> 5;
    int lane = threadIdx.x & 31;
    if (gw >= NB * NP) return;

    const float* row = logits + (size_t)gw * NC;
    float l0 = row[lane];
    float l1 = row[lane + 32];
    bool  has2 = (lane < NC - 64);           // lane < 27
    float l2 = has2 ? row[lane + 64] : -FLT_MAX;

    // local argmax with first-index tie break
    float bv = l0; int bi = lane;
    if (l1 > bv) { bv = l1; bi = lane + 32; }
    if (l2 > bv) { bv = l2; bi = lane + 64; }
    #pragma unroll
    for (int o = 16; o; o >>= 1) {
        float ov = __shfl_down_sync(0xffffffffu, bv, o);
        int   oi = __shfl_down_sync(0xffffffffu, bi, o);
        if (ov > bv || (ov == bv && oi < bi)) { bv = ov; bi = oi; }
    }
    bv = __shfl_sync(0xffffffffu, bv, 0);
    bi = __shfl_sync(0xffffffffu, bi, 0);

    float s = expf(l0 - bv) + expf(l1 - bv) + (has2 ? expf(l2 - bv) : 0.0f);
    #pragma unroll
    for (int o = 16; o; o >>= 1) s += __shfl_down_sync(0xffffffffu, s, o);

    if (lane == 0) {
        float score = 1.0f / s;
        int label = bi;
        int b = gw / NP;
        int valid = (label > 0) && (score > SCORE_THRESH);

        const float* p = props + (size_t)gw * 4;
        float x1 = p[0], y1 = p[1], x2 = p[2], y2 = p[3];
        float w = x2 - x1, h = y2 - y1;
        float cx = x1 + 0.5f * w, cy = y1 + 0.5f * h;

        const float* dd = deltas + (size_t)gw * (NC * 4) + 4 * label;
        float dx = dd[0], dy = dd[1];
        float dw = fminf(dd[2], BBOX_CLIP), dh = fminf(dd[3], BBOX_CLIP);
        float pcx = dx * w + cx, pcy = dy * h + cy;
        float pw = expf(dw) * w, ph = expf(dh) * h;
        float bx1 = pcx - 0.5f * pw, by1 = pcy - 0.5f * ph;
        float bx2 = pcx + 0.5f * pw, by2 = pcy + 0.5f * ph;

        float hb = (float)imsz[b * 2 + 0];
        float wb = (float)imsz[b * 2 + 1];
        bx1 = fminf(fmaxf(bx1, 0.0f), wb);
        by1 = fminf(fmaxf(by1, 0.0f), hb);
        bx2 = fminf(fmaxf(bx2, 0.0f), wb);
        by2 = fminf(fmaxf(by2, 0.0f), hb);

        g_boxes[gw]  = make_float4(bx1, by1, bx2, by2);
        g_scores[gw] = score;
        g_labels[gw] = valid ? label : 0;

        if (valid) {
            // exact max over valid box coords (all >= 0, float bits monotone)
            float mc = fmaxf(fmaxf(bx1, by1), fmaxf(bx2, by2));
            atomicMax(&g_maxc[b], __float_as_int(mc));
            int bc = b * 91 + label;
            int p2 = atomicAdd(&g_bcnt[bc], 1);
            if (p2 < BK) {
                int slot = bc * BK + p2;
                g_bbox[slot] = make_float4(bx1, by1, bx2, by2);
                g_bsc[slot]  = score;
                g_bidx[slot] = gw - b * NP;
            }
        }
    }
}

// ---------------- Kernel B: NMS, one warp per (image, class), registers only ----
// Writes kept keys into per-(image,class) segments. NO cross-warp atomics.
__global__ __launch_bounds__(256) void nms_class_kernel() {
    int gwarp = (blockIdx.x * blockDim.x + threadIdx.x) >> 5;
    int lane  = threadIdx.x & 31;
    if (gwarp >= NB * 90) return;
    int b = gwarp / 90;
    int c = 1 + gwarp % 90;
    int bc = b * 91 + c;

    int n = g_bcnt[bc];
    if (n > BK) n = BK;
    if (n == 0) {
        if (lane == 0) g_kkc[bc] = 0;
        return;
    }

    float K   = __int_as_float(g_maxc[b]) + 1.0f;
    float off = (float)c * K;    // label * (max_coord + 1), reference FP order

    float4 bxs[4]; float scs[4]; int idxs[4];
    unsigned alive = 0;
    #pragma unroll
    for (int j = 0; j < 4; ++j) {
        int e = j * 32 + lane;
        if (e < n) {
            float4 v = g_bbox[bc * BK + e];
            bxs[j] = make_float4(v.x + off, v.y + off, v.z + off, v.w + off);
            scs[j] = g_bsc[bc * BK + e];
            idxs[j] = g_bidx[bc * BK + e];
            alive |= (1u << j);
        } else {
            bxs[j] = make_float4(0.f, 0.f, 0.f, 0.f);
            scs[j] = 0.f; idxs[j] = 0;
        }
    }

    unsigned keptm = 0;
    while (true) {
        // per-lane best alive key: (~score_bits, orig_idx, slot)
        unsigned long long best = ~0ULL;
        #pragma unroll
        for (int j = 0; j < 4; ++j) {
            if (alive & (1u << j)) {
                unsigned long long k =
                    ((unsigned long long)(~__float_as_uint(scs[j])) << 20) |
                    ((unsigned long long)(unsigned)idxs[j] << 10) |
                    (unsigned long long)(unsigned)(j * 32 + lane);
                if (k < best) best = k;
            }
        }
        #pragma unroll
        for (int o = 16; o; o >>= 1) {
            unsigned long long ob = __shfl_xor_sync(0xffffffffu, best, o);
            if (ob < best) best = ob;
        }
        if (best == ~0ULL) break;

        int e   = (int)(best & 1023ULL);
        int js  = e >> 5;
        int src = e & 31;
        float4 own = (js == 0) ? bxs[0] : (js == 1) ? bxs[1] : (js == 2) ? bxs[2] : bxs[3];
        float4 A;
        A.x = __shfl_sync(0xffffffffu, own.x, src);
        A.y = __shfl_sync(0xffffffffu, own.y, src);
        A.z = __shfl_sync(0xffffffffu, own.z, src);
        A.w = __shfl_sync(0xffffffffu, own.w, src);
        if (lane == src) {
            alive &= ~(1u << js);
            keptm |= (1u << js);
        }
        float areaA = (A.z - A.x) * (A.w - A.y);

        #pragma unroll
        for (int j = 0; j < 4; ++j) {
            if (alive & (1u << j)) {
                float4 Bx = bxs[j];
                float areaB = (Bx.z - Bx.x) * (Bx.w - Bx.y);
                float ltx = fmaxf(A.x, Bx.x), lty = fmaxf(A.y, Bx.y);
                float rbx = fminf(A.z, Bx.z), rby = fminf(A.w, Bx.w);
                float wx = fmaxf(rbx - ltx, 0.0f), wy = fmaxf(rby - lty, 0.0f);
                float inter = wx * wy;
                float iou = inter / (areaA + areaB - inter + 1e-9f);
                if (iou > NMS_THRESH) alive &= ~(1u << j);
            }
        }
    }

    // warp-local compaction of kept keys into this (image,class) segment
    int kc = 0;
    #pragma unroll
    for (int j = 0; j < 4; ++j) {
        bool kept = (keptm >> j) & 1u;
        unsigned bal = __ballot_sync(0xffffffffu, kept);
        if (kept) {
            int pos = kc + __popc(bal & ((1u << lane) - 1u));
            g_kseg[bc * BK + pos] =
                ((unsigned long long)(~__float_as_uint(scs[j])) << 10) |
                (unsigned long long)(unsigned)idxs[j];
        }
        kc += __popc(bal);
    }
    if (lane == 0) g_kkc[bc] = kc;
}

// ---------------- Kernel C: per-image top-100 by rank counting ----------------
// 8 CTAs per image, 512 threads each; 4 threads cooperate per entry.
__global__ __launch_bounds__(512) void topk_rank_kernel(float* __restrict__ out) {
    const int img  = blockIdx.x >> 3;
    const int part = blockIdx.x & 7;
    const int t    = threadIdx.x;

    __shared__ unsigned long long s_keys[NP];   // 8 KB
    __shared__ int s_off[96];                   // inclusive prefix of class counts

    // load per-class kept counts (classes 1..90 -> idx 0..89)
    if (t < 90) s_off[t] = g_kkc[img * 91 + (t + 1)];
    __syncthreads();
    // Hillis-Steele inclusive scan over 90 values
    for (int d = 1; d < 90; d <<= 1) {
        int v = 0;
        if (t < 90 && t >= d) v = s_off[t - d];
        __syncthreads();
        if (t < 90) s_off[t] += v;
        __syncthreads();
    }
    const int M = s_off[89];

    // gather segments into contiguous key list: warp w handles classes w, w+16, ...
    {
        int warp = t >> 5, lane = t & 31;
        for (int ci = warp; ci < 90; ci += 16) {
            int start = (ci == 0) ? 0 : s_off[ci - 1];
            int cnt   = s_off[ci] - start;
            const unsigned long long* seg = g_kseg + (size_t)(img * 91 + ci + 1) * BK;
            for (int e = lane; e < cnt; e += 32)
                s_keys[start + e] = seg[e];
        }
    }
    __syncthreads();

    float* boxes_out  = out;
    float* scores_out = out + NB * MAX_DET * 4;
    float* labels_out = out + NB * MAX_DET * 5;

    const int filled = M < MAX_DET ? M : MAX_DET;
    if (part == 0 && t >= filled && t < MAX_DET) {
        int base = img * MAX_DET + t;
        boxes_out[base * 4 + 0] = 0.0f;
        boxes_out[base * 4 + 1] = 0.0f;
        boxes_out[base * 4 + 2] = 0.0f;
        boxes_out[base * 4 + 3] = 0.0f;
        scores_out[base] = 0.0f;
        labels_out[base] = -1.0f;
    }

    // 4 threads per entry: sub scans j = sub, sub+4, ...
    const int entry = part * 128 + (t >> 2);
    const int sub   = t & 3;
    if (entry < M) {
        unsigned long long mykey = s_keys[entry];
        int r = 0;
        for (int j = sub; j < M; j += 4)
            r += (s_keys[j] < mykey);
        r += __shfl_xor_sync(0xffffffffu, r, 1);
        r += __shfl_xor_sync(0xffffffffu, r, 2);
        if (sub == 0 && r < MAX_DET) {
            int idx = (int)(mykey & 1023ULL);
            int g = img * NP + idx;
            float4 v = g_boxes[g];
            int base = img * MAX_DET + r;
            boxes_out[base * 4 + 0] = v.x;
            boxes_out[base * 4 + 1] = v.y;
            boxes_out[base * 4 + 2] = v.z;
            boxes_out[base * 4 + 3] = v.w;
            scores_out[base] = g_scores[g];
            labels_out[base] = (float)g_labels[g];
        }
    }
}

// ---------------- launch ----------------
extern "C" void kernel_launch(void* const* d_in, const int* in_sizes, int n_in,
                              void* d_out, int out_size) {
    const float* class_logits  = (const float*)d_in[0];
    const float* bbox_deltas   = (const float*)d_in[1];
    const float* roi_proposals = (const float*)d_in[2];
    const int*   image_sizes   = (const int*)d_in[3];
    float* out = (float*)d_out;

    zero_kernel<<<3, 512>>>();

    int total_warps = NB * NP;
    int threads = 256;
    int blocks = (total_warps * 32 + threads - 1) / threads;
    score_decode_kernel<<<blocks, threads>>>(class_logits, bbox_deltas,
                                             roi_proposals, image_sizes);

    int nmsWarps = NB * 90;
    int nmsBlocks = (nmsWarps * 32 + 255) / 256;
    nms_class_kernel<<<nmsBlocks, 256>>>();

    topk_rank_kernel<<<NB * 8, 512>>>(out);
}